// round 1
// baseline (speedup 1.0000x reference)
#include <cuda_runtime.h>
#include <math.h>

#define NSLOPE 0.2f
#define EPSBN 1e-5f
#define NMAX 50000
#define EMAX 800000
#define TOTMAX (EMAX + NMAX)

// ------------------------------ scratch (device globals; no allocation) ---
__device__ float g_bufA[(size_t)NMAX * 256];
__device__ float g_bufB[(size_t)NMAX * 256];
__device__ float g_h2[(size_t)NMAX * 64];
__device__ float g_asrc[(size_t)NMAX * 4];
__device__ float g_adst[(size_t)NMAX * 4];
__device__ float g_m[(size_t)NMAX * 4];
__device__ float g_watt[(size_t)TOTMAX * 4];
__device__ int   g_deg[NMAX];
__device__ int   g_off[NMAX + 1];
__device__ int   g_cur[NMAX];
__device__ int   g_csrc[TOTMAX];
__device__ int   g_cdst[TOTMAX];
__device__ float g_AD[(size_t)EMAX * 64];      // reused as Y2 later
__device__ float g_Y1[(size_t)EMAX * 128];
__device__ float g_Wp[64 * 256];
__device__ float g_stats[512];
__device__ float g_bnsc[256];
__device__ float g_bnsh[256];

__device__ __forceinline__ float lrelu(float v) { return v > 0.f ? v : NSLOPE * v; }

// ------------------------------ generic fp32 GEMM: C = act(A@B + bias) ---
// A: MxK row-major, B: KxN row-major, C: MxN. N % 64 == 0, K % 16 == 0.
template <int ACT>
__global__ __launch_bounds__(256) void gemm_kernel(
    const float* __restrict__ A, const float* __restrict__ B,
    float* __restrict__ C, int M, int N, int K, const float* __restrict__ bias)
{
    __shared__ __align__(16) float As[16][132];
    __shared__ __align__(16) float Bs[16][64];
    const int t  = threadIdx.x;
    const int tx = t & 15, ty = t >> 4;
    const int rowBase = blockIdx.y * 128;
    const int colBase = blockIdx.x * 64;
    const int aRow = t >> 2;          // 0..63
    const int aCol = (t & 3) << 2;    // 0,4,8,12
    const int bRow = t >> 4;          // 0..15
    const int bCol = (t & 15) << 2;   // 0..60

    float acc[8][4];
#pragma unroll
    for (int i = 0; i < 8; i++)
#pragma unroll
        for (int j = 0; j < 4; j++) acc[i][j] = 0.f;

    for (int k0 = 0; k0 < K; k0 += 16) {
#pragma unroll
        for (int r = 0; r < 128; r += 64) {
            int gm = rowBase + aRow + r;
            float4 v = make_float4(0.f, 0.f, 0.f, 0.f);
            if (gm < M) v = *(const float4*)(A + (size_t)gm * K + k0 + aCol);
            As[aCol + 0][aRow + r] = v.x;
            As[aCol + 1][aRow + r] = v.y;
            As[aCol + 2][aRow + r] = v.z;
            As[aCol + 3][aRow + r] = v.w;
        }
        {
            float4 v = *(const float4*)(B + (size_t)(k0 + bRow) * N + colBase + bCol);
            *(float4*)&Bs[bRow][bCol] = v;
        }
        __syncthreads();
#pragma unroll
        for (int kk = 0; kk < 16; kk++) {
            float4 a0 = *(const float4*)&As[kk][ty * 8];
            float4 a1 = *(const float4*)&As[kk][ty * 8 + 4];
            float4 b0 = *(const float4*)&Bs[kk][tx * 4];
            float a[8] = {a0.x, a0.y, a0.z, a0.w, a1.x, a1.y, a1.z, a1.w};
            float b[4] = {b0.x, b0.y, b0.z, b0.w};
#pragma unroll
            for (int i = 0; i < 8; i++)
#pragma unroll
                for (int j = 0; j < 4; j++) acc[i][j] += a[i] * b[j];
        }
        __syncthreads();
    }

    float bi[4] = {0.f, 0.f, 0.f, 0.f};
    if (bias) {
#pragma unroll
        for (int j = 0; j < 4; j++) bi[j] = bias[colBase + tx * 4 + j];
    }
#pragma unroll
    for (int i = 0; i < 8; i++) {
        int gm = rowBase + ty * 8 + i;
        if (gm >= M) continue;
        float4 v;
        float r0 = acc[i][0] + bi[0], r1 = acc[i][1] + bi[1];
        float r2 = acc[i][2] + bi[2], r3 = acc[i][3] + bi[3];
        if (ACT) { r0 = lrelu(r0); r1 = lrelu(r1); r2 = lrelu(r2); r3 = lrelu(r3); }
        v.x = r0; v.y = r1; v.z = r2; v.w = r3;
        *(float4*)(C + (size_t)gm * N + colBase + tx * 4) = v;
    }
}

// ------------------------------ CSR build ---------------------------------
__global__ void init_deg_kernel(int* __restrict__ deg, int n)
{
    int i = blockIdx.x * blockDim.x + threadIdx.x;
    if (i < n) deg[i] = 1;  // self loop
}

__global__ void count_kernel(const int* __restrict__ ei, int E, int* __restrict__ deg)
{
    int i = blockIdx.x * blockDim.x + threadIdx.x;
    if (i < E) atomicAdd(&deg[ei[E + i]], 1);
}

__global__ void scan_kernel(const int* __restrict__ deg, int* __restrict__ off, int n)
{
    __shared__ int sh[1024];
    __shared__ int carry_s;
    int t = threadIdx.x;
    if (t == 0) carry_s = 0;
    __syncthreads();
    for (int base = 0; base < n; base += 1024) {
        int i = base + t;
        int v = (i < n) ? deg[i] : 0;
        sh[t] = v;
        __syncthreads();
        int sum = v;
        for (int ofs = 1; ofs < 1024; ofs <<= 1) {
            int add = (t >= ofs) ? sh[t - ofs] : 0;
            __syncthreads();
            sum += add;
            sh[t] = sum;
            __syncthreads();
        }
        int carry = carry_s;
        if (i < n) off[i] = carry + sum - v;  // exclusive
        __syncthreads();
        if (t == 1023) carry_s = carry + sum;
        __syncthreads();
    }
    if (t == 0) off[n] = carry_s;
}

__global__ void copy_cur_kernel(const int* __restrict__ off, int* __restrict__ cur, int n)
{
    int i = blockIdx.x * blockDim.x + threadIdx.x;
    if (i < n) cur[i] = off[i];
}

__global__ void scatter_edges_kernel(const int* __restrict__ ei, int E,
                                     int* __restrict__ cur,
                                     int* __restrict__ csrc, int* __restrict__ cdst)
{
    int i = blockIdx.x * blockDim.x + threadIdx.x;
    if (i >= E) return;
    int d = ei[E + i];
    int pos = atomicAdd(&cur[d], 1);
    csrc[pos] = ei[i];
    cdst[pos] = d;
}

__global__ void scatter_loops_kernel(int N, int* __restrict__ cur,
                                     int* __restrict__ csrc, int* __restrict__ cdst)
{
    int n = blockIdx.x * blockDim.x + threadIdx.x;
    if (n >= N) return;
    int pos = atomicAdd(&cur[n], 1);
    csrc[pos] = n;
    cdst[pos] = n;
}

// ------------------------------ GAT attention -----------------------------
__global__ void alpha_kernel(const float* __restrict__ h,
                             const float* __restrict__ aw_s, const float* __restrict__ aw_d,
                             float* __restrict__ asrc, float* __restrict__ adst, int N)
{
    int id = blockIdx.x * blockDim.x + threadIdx.x;  // (n,h)
    if (id >= N * 4) return;
    int n = id >> 2, hh = id & 3;
    const float4* row = (const float4*)(h + (size_t)n * 256 + hh * 64);
    const float4* ws  = (const float4*)(aw_s + hh * 64);
    const float4* wd  = (const float4*)(aw_d + hh * 64);
    float sa = 0.f, sb = 0.f;
#pragma unroll
    for (int q = 0; q < 16; q++) {
        float4 v = row[q];
        float4 a = ws[q], b = wd[q];
        sa += v.x * a.x + v.y * a.y + v.z * a.z + v.w * a.w;
        sb += v.x * b.x + v.y * b.y + v.z * b.z + v.w * b.w;
    }
    asrc[id] = sa;
    adst[id] = sb;
}

__global__ void gat_max_kernel(const float4* __restrict__ asrc4, const float4* __restrict__ adst4,
                               const int* __restrict__ off, const int* __restrict__ csrc,
                               float4* __restrict__ m4, int N)
{
    int w = (blockIdx.x * blockDim.x + threadIdx.x) >> 5;
    int lane = threadIdx.x & 31;
    if (w >= N) return;
    float4 ad = adst4[w];
    float m0 = -1e30f, m1 = -1e30f, m2 = -1e30f, m3 = -1e30f;
    int hi = off[w + 1];
    for (int p = off[w] + lane; p < hi; p += 32) {
        int s = csrc[p];
        float4 as = asrc4[s];
        float e0 = lrelu(as.x + ad.x), e1 = lrelu(as.y + ad.y);
        float e2 = lrelu(as.z + ad.z), e3 = lrelu(as.w + ad.w);
        m0 = fmaxf(m0, e0); m1 = fmaxf(m1, e1); m2 = fmaxf(m2, e2); m3 = fmaxf(m3, e3);
    }
#pragma unroll
    for (int o = 16; o > 0; o >>= 1) {
        m0 = fmaxf(m0, __shfl_xor_sync(0xffffffffu, m0, o));
        m1 = fmaxf(m1, __shfl_xor_sync(0xffffffffu, m1, o));
        m2 = fmaxf(m2, __shfl_xor_sync(0xffffffffu, m2, o));
        m3 = fmaxf(m3, __shfl_xor_sync(0xffffffffu, m3, o));
    }
    if (lane == 0) m4[w] = make_float4(m0, m1, m2, m3);
}

__global__ void watt_kernel(const float4* __restrict__ asrc4, const float4* __restrict__ adst4,
                            const float4* __restrict__ m4,
                            const int* __restrict__ csrc, const int* __restrict__ cdst,
                            float4* __restrict__ watt4, int tot)
{
    int p = blockIdx.x * blockDim.x + threadIdx.x;
    if (p >= tot) return;
    int s = csrc[p], d = cdst[p];
    float4 as = asrc4[s], ad = adst4[d], mm = m4[d];
    float4 w;
    w.x = expf(lrelu(as.x + ad.x) - mm.x);
    w.y = expf(lrelu(as.y + ad.y) - mm.y);
    w.z = expf(lrelu(as.z + ad.z) - mm.z);
    w.w = expf(lrelu(as.w + ad.w) - mm.w);
    watt4[p] = w;
}

__global__ __launch_bounds__(256) void gat_aggregate_kernel(
    const float* __restrict__ h, const float* __restrict__ watt,
    const int* __restrict__ off, const int* __restrict__ csrc,
    const float* __restrict__ bias, float* __restrict__ out, int concat)
{
    int d = blockIdx.x;
    int t = threadIdx.x;       // 256
    int hh = t >> 6;
    int lo = off[d], hi = off[d + 1];
    float acc = 0.f, den = 0.f;
    for (int p = lo; p < hi; ++p) {
        int s = csrc[p];
        float w = watt[p * 4 + hh];
        den += w;
        acc += w * h[(size_t)s * 256 + t];
    }
    acc /= den;
    if (concat) {
        out[(size_t)d * 256 + t] = acc + bias[t];
    } else {
        __shared__ float red[256];
        red[t] = acc;
        __syncthreads();
        if (t < 64)
            out[(size_t)d * 64 + t] =
                0.25f * (red[t] + red[t + 64] + red[t + 128] + red[t + 192]) + bias[t];
    }
}

// ------------------------------ BatchNorm ---------------------------------
__global__ void zero_kernel(float* __restrict__ p, int n)
{
    int i = blockIdx.x * blockDim.x + threadIdx.x;
    if (i < n) p[i] = 0.f;
}

__global__ void bn_stats_kernel(const float* __restrict__ X, int rows, int cols,
                                float* __restrict__ stats, int rowsPerBlock)
{
    int t = threadIdx.x;  // 256
    int c = t % cols;
    int rsub = t / cols;
    int rstep = 256 / cols;
    int r0 = blockIdx.x * rowsPerBlock;
    int r1 = r0 + rowsPerBlock; if (r1 > rows) r1 = rows;
    float s = 0.f, s2 = 0.f;
    for (int r = r0 + rsub; r < r1; r += rstep) {
        float v = X[(size_t)r * cols + c];
        s += v;
        s2 += v * v;
    }
    atomicAdd(&stats[c], s);
    atomicAdd(&stats[cols + c], s2);
}

__global__ void bn_final_kernel(const float* __restrict__ stats,
                                const float* __restrict__ g, const float* __restrict__ be,
                                int rows, int cols,
                                float* __restrict__ sc, float* __restrict__ sh)
{
    int c = threadIdx.x;
    if (c >= cols) return;
    float inv = 1.f / (float)rows;
    float mean = stats[c] * inv;
    float var = stats[cols + c] * inv - mean * mean;
    float scale = g[c] * rsqrtf(var + EPSBN);
    sc[c] = scale;
    sh[c] = be[c] - mean * scale;
}

__global__ void bn_apply_kernel(float* __restrict__ X, int n, int cols,
                                const float* __restrict__ sc, const float* __restrict__ sh,
                                int act)
{
    int i = blockIdx.x * blockDim.x + threadIdx.x;
    if (i >= n) return;
    int c = i % cols;
    float v = X[i] * sc[c] + sh[c];
    if (act) v = lrelu(v);
    X[i] = v;
}

// ------------------------------ Edge MLP ----------------------------------
__global__ void build_wp_kernel(const float* __restrict__ Wm1, float* __restrict__ Wp)
{
    int idx = blockIdx.x * blockDim.x + threadIdx.x;  // 64*256
    if (idx >= 64 * 256) return;
    int i = idx >> 8, j = idx & 255;
    Wp[idx] = (j < 128) ? Wm1[i * 128 + j] : Wm1[(64 + i) * 128 + (j - 128)];
}

__global__ void absdiff_kernel(const float* __restrict__ h2, const int* __restrict__ ei,
                               float* __restrict__ AD, int E)
{
    int idx = blockIdx.x * blockDim.x + threadIdx.x;  // E*64
    if (idx >= E * 64) return;
    int e = idx >> 6, i = idx & 63;
    int s = ei[e], d = ei[E + e];
    AD[idx] = fabsf(h2[(size_t)s * 64 + i] - h2[(size_t)d * 64 + i]);
}

__global__ void e2_epilogue_kernel(float* __restrict__ Y1, const float* __restrict__ PQ,
                                   const float* __restrict__ ea,
                                   const float* __restrict__ w192, const float* __restrict__ bm1,
                                   const int* __restrict__ ei, int E)
{
    int idx = blockIdx.x * blockDim.x + threadIdx.x;  // E*128
    if (idx >= E * 128) return;
    int e = idx >> 7, j = idx & 127;
    int s = ei[e], d = ei[E + e];
    float v = Y1[idx] + PQ[(size_t)s * 256 + j] + PQ[(size_t)d * 256 + 128 + j]
              + ea[e] * w192[j] + bm1[j];
    Y1[idx] = lrelu(v);
}

__global__ void final_kernel(const float* __restrict__ Y2, const float* __restrict__ wm3,
                             const float* __restrict__ bm3, float* __restrict__ out, int E)
{
    int gw = (blockIdx.x * blockDim.x + threadIdx.x) >> 5;
    int lane = threadIdx.x & 31;
    if (gw >= E) return;
    const float* row = Y2 + (size_t)gw * 64;
    float v = row[lane] * wm3[lane] + row[lane + 32] * wm3[lane + 32];
#pragma unroll
    for (int o = 16; o > 0; o >>= 1) v += __shfl_xor_sync(0xffffffffu, v, o);
    if (lane == 0) out[gw] = v + bm3[0];
}

// ------------------------------ host orchestration ------------------------
extern "C" void kernel_launch(void* const* d_in, const int* in_sizes, int n_in,
                              void* d_out, int out_size)
{
    const float* x  = (const float*)d_in[0];
    const int*   ei = (const int*)d_in[1];
    const float* ea = (const float*)d_in[2];
    const int N = in_sizes[0] / 128;
    const int E = in_sizes[2];

    const float *W0, *as0, *ad0, *b0, *g0, *be0;
    const float *W1, *as1, *ad1, *b1, *g1, *be1;
    const float *W2, *as2, *ad2, *b2, *g2, *be2;
    if (in_sizes[7] == 256 * 256) {
        // setup_inputs dict insertion order
        W0 = (const float*)d_in[3];  as0 = (const float*)d_in[4];  ad0 = (const float*)d_in[5];  b0 = (const float*)d_in[6];
        W1 = (const float*)d_in[7];  as1 = (const float*)d_in[8];  ad1 = (const float*)d_in[9];  b1 = (const float*)d_in[10];
        W2 = (const float*)d_in[11]; as2 = (const float*)d_in[12]; ad2 = (const float*)d_in[13]; b2 = (const float*)d_in[14];
        g0 = (const float*)d_in[15]; be0 = (const float*)d_in[16];
        g1 = (const float*)d_in[17]; be1 = (const float*)d_in[18];
        g2 = (const float*)d_in[19]; be2 = (const float*)d_in[20];
    } else {
        // reference() signature order
        W0 = (const float*)d_in[3];  as0 = (const float*)d_in[4];  ad0 = (const float*)d_in[5];  b0 = (const float*)d_in[6];
        g0 = (const float*)d_in[7];  be0 = (const float*)d_in[8];
        W1 = (const float*)d_in[9];  as1 = (const float*)d_in[10]; ad1 = (const float*)d_in[11]; b1 = (const float*)d_in[12];
        g1 = (const float*)d_in[13]; be1 = (const float*)d_in[14];
        W2 = (const float*)d_in[15]; as2 = (const float*)d_in[16]; ad2 = (const float*)d_in[17]; b2 = (const float*)d_in[18];
        g2 = (const float*)d_in[19]; be2 = (const float*)d_in[20];
    }
    const float* Wm1 = (const float*)d_in[21];
    const float* bm1 = (const float*)d_in[22];
    const float* Wm2 = (const float*)d_in[23];
    const float* bm2 = (const float*)d_in[24];
    const float* Wm3 = (const float*)d_in[25];
    const float* bm3 = (const float*)d_in[26];
    float* out = (float*)d_out;

    float *bufA, *bufB, *h2, *asrc, *adst, *m, *watt, *AD, *Y1, *Wp, *stats, *bnsc, *bnsh;
    int *deg, *off, *cur, *csrc, *cdst;
    cudaGetSymbolAddress((void**)&bufA, g_bufA);
    cudaGetSymbolAddress((void**)&bufB, g_bufB);
    cudaGetSymbolAddress((void**)&h2, g_h2);
    cudaGetSymbolAddress((void**)&asrc, g_asrc);
    cudaGetSymbolAddress((void**)&adst, g_adst);
    cudaGetSymbolAddress((void**)&m, g_m);
    cudaGetSymbolAddress((void**)&watt, g_watt);
    cudaGetSymbolAddress((void**)&AD, g_AD);
    cudaGetSymbolAddress((void**)&Y1, g_Y1);
    cudaGetSymbolAddress((void**)&Wp, g_Wp);
    cudaGetSymbolAddress((void**)&stats, g_stats);
    cudaGetSymbolAddress((void**)&bnsc, g_bnsc);
    cudaGetSymbolAddress((void**)&bnsh, g_bnsh);
    cudaGetSymbolAddress((void**)&deg, g_deg);
    cudaGetSymbolAddress((void**)&off, g_off);
    cudaGetSymbolAddress((void**)&cur, g_cur);
    cudaGetSymbolAddress((void**)&csrc, g_csrc);
    cudaGetSymbolAddress((void**)&cdst, g_cdst);

    const int tot = E + N;

    auto gemm = [&](const float* A, const float* B, float* C, int M, int Nc, int K,
                    const float* bias, int act) {
        dim3 grid(Nc / 64, (M + 127) / 128);
        if (act) gemm_kernel<1><<<grid, 256>>>(A, B, C, M, Nc, K, bias);
        else     gemm_kernel<0><<<grid, 256>>>(A, B, C, M, Nc, K, bias);
    };

    // ---- CSR build (dst-major, self-loops appended per node) ----
    init_deg_kernel<<<(N + 255) / 256, 256>>>(deg, N);
    count_kernel<<<(E + 255) / 256, 256>>>(ei, E, deg);
    scan_kernel<<<1, 1024>>>(deg, off, N);
    copy_cur_kernel<<<(N + 255) / 256, 256>>>(off, cur, N);
    scatter_edges_kernel<<<(E + 255) / 256, 256>>>(ei, E, cur, csrc, cdst);
    scatter_loops_kernel<<<(N + 255) / 256, 256>>>(N, cur, csrc, cdst);

    auto gat_layer = [&](const float* Xin, int Kin, const float* W,
                         const float* aws, const float* awd, const float* bias,
                         float* hbuf, float* outbuf, int concat) {
        gemm(Xin, W, hbuf, N, 256, Kin, nullptr, 0);
        alpha_kernel<<<(N * 4 + 255) / 256, 256>>>(hbuf, aws, awd, asrc, adst, N);
        gat_max_kernel<<<(N * 32 + 255) / 256, 256>>>((const float4*)asrc, (const float4*)adst,
                                                      off, csrc, (float4*)m, N);
        watt_kernel<<<(tot + 255) / 256, 256>>>((const float4*)asrc, (const float4*)adst,
                                                (const float4*)m, csrc, cdst, (float4*)watt, tot);
        gat_aggregate_kernel<<<N, 256>>>(hbuf, watt, off, csrc, bias, outbuf, concat);
    };

    auto bnorm = [&](float* X, int cols, const float* g, const float* be, int act) {
        zero_kernel<<<1, 512>>>(stats, 2 * cols);
        const int rpb = 256;
        bn_stats_kernel<<<(N + rpb - 1) / rpb, 256>>>(X, N, cols, stats, rpb);
        bn_final_kernel<<<1, cols>>>(stats, g, be, N, cols, bnsc, bnsh);
        bn_apply_kernel<<<(N * cols + 255) / 256, 256>>>(X, N * cols, cols, bnsc, bnsh, act);
    };

    // ---- 3 GAT layers ----
    gat_layer(x, 128, W0, as0, ad0, b0, bufA, bufB, 1);
    bnorm(bufB, 256, g0, be0, 1);

    gat_layer(bufB, 256, W1, as1, ad1, b1, bufA, bufB, 1);
    bnorm(bufB, 256, g1, be1, 1);

    gat_layer(bufB, 256, W2, as2, ad2, b2, bufA, h2, 0);
    bnorm(h2, 64, g2, be2, 0);

    // ---- Edge MLP ----
    // P|Q = h2 @ [Wm1[0:64,:], Wm1[64:128,:]]   (node-level precompute)
    build_wp_kernel<<<(64 * 256 + 255) / 256, 256>>>(Wm1, Wp);
    gemm(h2, Wp, bufA, N, 256, 64, nullptr, 0);  // bufA = PQ (N x 256)

    absdiff_kernel<<<((size_t)E * 64 + 255) / 256, 256>>>(h2, ei, AD, E);
    gemm(AD, Wm1 + 128 * 128, Y1, E, 128, 64, nullptr, 0);  // Y1 = AD @ C
    e2_epilogue_kernel<<<((size_t)E * 128 + 255) / 256, 256>>>(Y1, bufA, ea, Wm1 + 192 * 128,
                                                               bm1, ei, E);
    gemm(Y1, Wm2, AD, E, 64, 128, bm2, 1);  // Y2 (reusing AD) = leaky(Y1@Wm2 + bm2)
    final_kernel<<<((size_t)E * 32 + 255) / 256, 256>>>(AD, Wm3, bm3, out, E);
}